// round 11
// baseline (speedup 1.0000x reference)
#include <cuda_runtime.h>
#include <math.h>

#define FULL_MASK 0xffffffffu

static constexpr int S_UNIFORM = 256;   // coarse samples per ray
static constexpr int N_IMP     = 128;   // importance samples per ray
static constexpr int OUT_COLS  = 4 + N_IMP;  // 132
static constexpr int WARPS_PER_BLK = 8;
static constexpr float TRUNC   = 0.015625f;  // 2/512*4

__global__ __launch_bounds__(WARPS_PER_BLK * 32, 8)
void tsdf_render_kernel(const float* __restrict__ occ,
                        const float* __restrict__ zvals,
                        const float* __restrict__ sdf,
                        const float* __restrict__ rgbs,
                        float* __restrict__ out,
                        int n_rays)
{
    __shared__ float cdf_s [WARPS_PER_BLK][256];  // [0..254]=cdf (255 unused)
    __shared__ float zmid_s[WARPS_PER_BLK][256];  // z midpoints [0..254]

    const int warp = threadIdx.x >> 5;
    const int lane = threadIdx.x & 31;
    const int ray  = blockIdx.x * WARPS_PER_BLK + warp;
    if (ray >= n_rays) return;

    float* cdf  = cdf_s[warp];
    float* zmid = zmid_s[warp];

    const float* occ_row = occ   + (size_t)ray * S_UNIFORM;
    const float* z_row   = zvals + (size_t)ray * S_UNIFORM;

    // ---------------- Phase A: coarse occupancy -> normalized CDF + zmid ----------------
    float4 o0 = __ldg((const float4*)(occ_row + lane * 8));
    float4 o1 = __ldg((const float4*)(occ_row + lane * 8 + 4));
    float4 zA = __ldg((const float4*)(z_row + lane * 8));
    float4 zB = __ldg((const float4*)(z_row + lane * 8 + 4));

    // z midpoints: zmid[g] = 0.5*(z[g]+z[g+1]); chunk boundary via shuffle
    float znext = __shfl_down_sync(FULL_MASK, zA.x, 1);  // lane31: self (zmid[255] unused)
    {
        float4 m0, m1;
        m0.x = 0.5f * (zA.x + zA.y);
        m0.y = 0.5f * (zA.y + zA.z);
        m0.z = 0.5f * (zA.z + zA.w);
        m0.w = 0.5f * (zA.w + zB.x);
        m1.x = 0.5f * (zB.x + zB.y);
        m1.y = 0.5f * (zB.y + zB.z);
        m1.z = 0.5f * (zB.z + zB.w);
        m1.w = 0.5f * (zB.w + znext);
        ((float4*)(zmid + lane * 8))[0] = m0;
        ((float4*)(zmid + lane * 8))[1] = m1;
    }

    float oc[8] = {o0.x, o0.y, o0.z, o0.w, o1.x, o1.y, o1.z, o1.w};
    float a[8], f[8];
#pragma unroll
    for (int j = 0; j < 8; j++) {
        float e = __expf(-10.0f * oc[j]);         // sigmoid(10*occ) = 1/(1+e)
        float d = __fdividef(1.0f, 1.0f + e);
        a[j] = d;
        f[j] = (1.0f - d) + 1e-10f;               // ref order: 1 - alpha + 1e-10
    }

    // multiplicative exclusive warp scan for transmittance
    float ptot = 1.0f;
#pragma unroll
    for (int j = 0; j < 8; j++) ptot *= f[j];
    float v = ptot;
#pragma unroll
    for (int off = 1; off < 32; off <<= 1) {
        float t = __shfl_up_sync(FULL_MASK, v, off);
        if (lane >= off) v *= t;
    }
    float pexcl = __shfl_up_sync(FULL_MASK, v, 1);
    if (lane == 0) pexcl = 1.0f;

    // masked cumsum of (w_u + 1e-5) over g in [1, 254] -> unnormalized cdf
    float trans = pexcl;
    float c[8];
    float ssum = 0.0f;
#pragma unroll
    for (int j = 0; j < 8; j++) {
        int g = lane * 8 + j;
        float w = a[j] * trans;                   // w_u[g]
        trans *= f[j];
        float wv = (g >= 1 && g <= 254) ? (w + 1e-5f) : 0.0f;
        ssum += wv;
        c[j] = ssum;
    }
    float sv = ssum;
#pragma unroll
    for (int off = 1; off < 32; off <<= 1) {
        float t = __shfl_up_sync(FULL_MASK, sv, off);
        if (lane >= off) sv += t;
    }
    float total = __shfl_sync(FULL_MASK, sv, 31);
    float sexcl = __shfl_up_sync(FULL_MASK, sv, 1);
    if (lane == 0) sexcl = 0.0f;

    float inv_total = 1.0f / total;               // total >= 254e-5 > 0
    float vals[8];
#pragma unroll
    for (int j = 0; j < 8; j++) vals[j] = (sexcl + c[j]) * inv_total;
    // g==0 -> exact 0 (sexcl=0, c[0]=0).
    ((float4*)(cdf + lane * 8))[0] = make_float4(vals[0], vals[1], vals[2], vals[3]);
    ((float4*)(cdf + lane * 8))[1] = make_float4(vals[4], vals[5], vals[6], vals[7]);

    // tree levels s=128..8 probe positions (2m+1)*s-1 == 8*L+7  -> lane L's vals[7]
    // tree level  s=4      probe positions 8*m+3               -> lane m's vals[3]
    const float cmax = vals[7];
    const float cmid = vals[3];
    __syncwarp();

    // ---------------- Phase B: inverse-CDF importance sampling ----------------
    // lane handles i = lane*4 + k; z samples stay in registers.
    float zk[4];
#pragma unroll
    for (int k = 0; k < 4; k++) {
        int i = lane * 4 + k;
        float u = (i == 127) ? 1.0f : (float)i * (1.0f / 127.0f);
        // searchsorted(cdf[0..254], u, side='right') via binary search on answer.
        // cb = cdf[ind-1] (last accepted), ca = cdf[ind] (last rejected; rejected
        // probe positions strictly decrease so last reject is at ind_final).
        int ind = 0;
        float cb = 0.0f;
        float ca = __int_as_float(0x7f800000);
        // levels s=128..8: values live in registers across the warp -> shuffle
#pragma unroll
        for (int s = 128; s >= 8; s >>= 1) {
            int src = ((ind + s) >> 3) - 1;            // probe p = ind+s-1 = 8*src+7
            float cv = __shfl_sync(FULL_MASK, cmax, src);
            if (cv <= u) { ind += s; cb = cv; } else { ca = cv; }
        }
        {   // level s=4: probe p = ind+3 = 8*(ind>>3)+3
            float cv = __shfl_sync(FULL_MASK, cmid, ind >> 3);
            if (cv <= u) { ind += 4; cb = cv; } else { ca = cv; }
        }
        // levels s=2,1: fine positions -> shared
#pragma unroll
        for (int s = 2; s >= 1; s >>= 1) {
            float cv = cdf[ind + s - 1];               // max probe idx = 254
            if (cv <= u) { ind += s; cb = cv; } else { ca = cv; }
        }
        // ind >= 1 always (final s=1 probe at p=0 accepts since cdf[0]=0 <= u)
        // ind==255 -> ca=+inf -> t=0 -> bins_b (matches ref denom<1e-5 path)
        float bb = zmid[ind - 1];
        float ba = zmid[min(ind, 254)];                // ind==255 reads 254 == bb
        float denom = ca - cb;
        if (denom < 1e-5f) denom = 1.0f;
        float t = __fdividef(u - cb, denom);
        zk[k] = bb + t * (ba - bb);
    }

    // ---------------- Phase C: TSDF weights ----------------
    const float* sdf_row = sdf + (size_t)ray * N_IMP;
    float4 s4 = __ldg((const float4*)(sdf_row + lane * 4));
    float s[4] = {s4.x, s4.y, s4.z, s4.w};
    float al[4];
#pragma unroll
    for (int k = 0; k < 4; k++) {
        float x = s[k] * (1.0f / TRUNC);           // exact: / 2^-6
        // sigmoid(x)*sigmoid(-x) = e*d^2, e = exp(-|x|), d = 1/(1+e)  (stable, even)
        float e = __expf(-fabsf(x));
        float d = __fdividef(1.0f, 1.0f + e);
        al[k] = e * d * d;
    }

    // first zero-crossing index (argmax of sign_mask; 0 if none)
    float snext = __shfl_down_sync(FULL_MASK, s[0], 1);
    int firstc = 1000;
#pragma unroll
    for (int k = 0; k < 3; k++) {
        if (s[k] * s[k + 1] < 0.0f) firstc = min(firstc, lane * 4 + k);
    }
    if (lane < 31 && s[3] * snext < 0.0f) firstc = min(firstc, lane * 4 + 3);
#pragma unroll
    for (int off = 16; off; off >>= 1)
        firstc = min(firstc, __shfl_xor_sync(FULL_MASK, firstc, off));
    int ind0 = (firstc >= 1000) ? 0 : firstc;      // uniform across warp

    // broadcast z_samples[ind0] from its owner lane's registers
    int sub = ind0 & 3;
    float zc = (sub & 2) ? ((sub & 1) ? zk[3] : zk[2])
                         : ((sub & 1) ? zk[1] : zk[0]);
    float zmin = __shfl_sync(FULL_MASK, zc, ind0 >> 2);
    float thr  = zmin + TRUNC;                     // sc_factor = 1.0

    float wsum = 0.0f;
#pragma unroll
    for (int k = 0; k < 4; k++) {
        if (!(zk[k] < thr)) al[k] = 0.0f;          // trunc_mask
        wsum += al[k];
    }
#pragma unroll
    for (int off = 16; off; off >>= 1)
        wsum += __shfl_xor_sync(FULL_MASK, wsum, off);
    float inv = 1.0f / (wsum + 1e-8f);
    float w0 = al[0] * inv, w1 = al[1] * inv, w2 = al[2] * inv, w3 = al[3] * inv;

    // ---------------- Phase D: composite ----------------
    const float* rgb_row = rgbs + (size_t)ray * (N_IMP * 3) + lane * 12;
    float4 q0 = __ldg((const float4*)(rgb_row));
    float4 q1 = __ldg((const float4*)(rgb_row + 4));
    float4 q2 = __ldg((const float4*)(rgb_row + 8));

    float r   = w0 * q0.x + w1 * q0.w + w2 * q1.z + w3 * q2.y;
    float g   = w0 * q0.y + w1 * q1.x + w2 * q1.w + w3 * q2.z;
    float b   = w0 * q0.z + w1 * q1.y + w2 * q2.x + w3 * q2.w;
    float dep = w0 * zk[0] + w1 * zk[1] + w2 * zk[2] + w3 * zk[3];
#pragma unroll
    for (int off = 16; off; off >>= 1) {
        r   += __shfl_xor_sync(FULL_MASK, r,   off);
        g   += __shfl_xor_sync(FULL_MASK, g,   off);
        b   += __shfl_xor_sync(FULL_MASK, b,   off);
        dep += __shfl_xor_sync(FULL_MASK, dep, off);
    }

    float* orow = out + (size_t)ray * OUT_COLS;
    if (lane == 0) {
        float4 h;
        h.x = fminf(fmaxf(r, 0.0f), 1.0f);
        h.y = fminf(fmaxf(g, 0.0f), 1.0f);
        h.z = fminf(fmaxf(b, 0.0f), 1.0f);
        h.w = dep;
        *(float4*)orow = h;                        // row base 528B-aligned
    }
    *(float4*)(orow + 4 + lane * 4) = make_float4(w0, w1, w2, w3);
}

extern "C" void kernel_launch(void* const* d_in, const int* in_sizes, int n_in,
                              void* d_out, int out_size)
{
    const float* occ   = (const float*)d_in[0];  // [N, 256]
    const float* zvals = (const float*)d_in[1];  // [N, 256]
    const float* sdfp  = (const float*)d_in[2];  // [N, 128]
    const float* rgbs  = (const float*)d_in[3];  // [N, 128, 3]
    float* out = (float*)d_out;                  // [N, 132]

    int n_rays = in_sizes[0] / S_UNIFORM;
    int blocks = (n_rays + WARPS_PER_BLK - 1) / WARPS_PER_BLK;
    tsdf_render_kernel<<<blocks, WARPS_PER_BLK * 32>>>(occ, zvals, sdfp, rgbs, out, n_rays);
}

// round 13
// speedup vs baseline: 1.4947x; 1.4947x over previous
#include <cuda_runtime.h>
#include <math.h>

#define FULL_MASK 0xffffffffu

static constexpr int S_UNIFORM = 256;   // coarse samples per ray
static constexpr int N_IMP     = 128;   // importance samples per ray
static constexpr int OUT_COLS  = 4 + N_IMP;  // 132
static constexpr int WARPS_PER_BLK = 8;
static constexpr float TRUNC   = 0.015625f;  // 2/512*4

__global__ __launch_bounds__(WARPS_PER_BLK * 32, 8)
void tsdf_render_kernel(const float* __restrict__ occ,
                        const float* __restrict__ zvals,
                        const float* __restrict__ sdf,
                        const float* __restrict__ rgbs,
                        float* __restrict__ out,
                        int n_rays)
{
    __shared__ float cdf_s [WARPS_PER_BLK][256];  // [0..254]=cdf, [255]=+inf pad
    __shared__ float zmid_s[WARPS_PER_BLK][256];  // z midpoints [0..254]

    const int warp = threadIdx.x >> 5;
    const int lane = threadIdx.x & 31;
    const int ray  = blockIdx.x * WARPS_PER_BLK + warp;
    if (ray >= n_rays) return;

    float* cdf  = cdf_s[warp];
    float* zmid = zmid_s[warp];

    const float* occ_row = occ   + (size_t)ray * S_UNIFORM;
    const float* z_row   = zvals + (size_t)ray * S_UNIFORM;

    // ---------------- Phase A: coarse occupancy -> normalized CDF + zmid ----------------
    float4 o0 = __ldg((const float4*)(occ_row + lane * 8));
    float4 o1 = __ldg((const float4*)(occ_row + lane * 8 + 4));
    float4 zA = __ldg((const float4*)(z_row + lane * 8));
    float4 zB = __ldg((const float4*)(z_row + lane * 8 + 4));

    // z midpoints: zmid[g] = 0.5*(z[g]+z[g+1]); chunk boundary via shuffle
    float znext = __shfl_down_sync(FULL_MASK, zA.x, 1);  // lane31: self (zmid[255] unused)
    {
        float4 m0, m1;
        m0.x = 0.5f * (zA.x + zA.y);
        m0.y = 0.5f * (zA.y + zA.z);
        m0.z = 0.5f * (zA.z + zA.w);
        m0.w = 0.5f * (zA.w + zB.x);
        m1.x = 0.5f * (zB.x + zB.y);
        m1.y = 0.5f * (zB.y + zB.z);
        m1.z = 0.5f * (zB.z + zB.w);
        m1.w = 0.5f * (zB.w + znext);
        ((float4*)(zmid + lane * 8))[0] = m0;
        ((float4*)(zmid + lane * 8))[1] = m1;
    }

    float oc[8] = {o0.x, o0.y, o0.z, o0.w, o1.x, o1.y, o1.z, o1.w};
    float a[8], f[8];
#pragma unroll
    for (int j = 0; j < 8; j++) {
        float e = __expf(-10.0f * oc[j]);         // sigmoid(10*occ) = 1/(1+e)
        float d = __fdividef(1.0f, 1.0f + e);
        a[j] = d;
        f[j] = (1.0f - d) + 1e-10f;               // ref order: 1 - alpha + 1e-10
    }

    // multiplicative exclusive warp scan for transmittance
    float ptot = 1.0f;
#pragma unroll
    for (int j = 0; j < 8; j++) ptot *= f[j];
    float v = ptot;
#pragma unroll
    for (int off = 1; off < 32; off <<= 1) {
        float t = __shfl_up_sync(FULL_MASK, v, off);
        if (lane >= off) v *= t;
    }
    float pexcl = __shfl_up_sync(FULL_MASK, v, 1);
    if (lane == 0) pexcl = 1.0f;

    // masked cumsum of (w_u + 1e-5) over g in [1, 254] -> unnormalized cdf
    float trans = pexcl;
    float c[8];
    float ssum = 0.0f;
#pragma unroll
    for (int j = 0; j < 8; j++) {
        int g = lane * 8 + j;
        float w = a[j] * trans;                   // w_u[g]
        trans *= f[j];
        float wv = (g >= 1 && g <= 254) ? (w + 1e-5f) : 0.0f;
        ssum += wv;
        c[j] = ssum;
    }
    float sv = ssum;
#pragma unroll
    for (int off = 1; off < 32; off <<= 1) {
        float t = __shfl_up_sync(FULL_MASK, sv, off);
        if (lane >= off) sv += t;
    }
    float total = __shfl_sync(FULL_MASK, sv, 31);
    float sexcl = __shfl_up_sync(FULL_MASK, sv, 1);
    if (lane == 0) sexcl = 0.0f;

    float inv_total = 1.0f / total;               // total >= 254e-5 > 0
    float vals[8];
#pragma unroll
    for (int j = 0; j < 8; j++) vals[j] = (sexcl + c[j]) * inv_total;
    // g==0 -> exact 0.  g==255 -> +inf sentinel (rejects probes)
    if (lane == 31) vals[7] = __int_as_float(0x7f800000);
    ((float4*)(cdf + lane * 8))[0] = make_float4(vals[0], vals[1], vals[2], vals[3]);
    ((float4*)(cdf + lane * 8))[1] = make_float4(vals[4], vals[5], vals[6], vals[7]);
    __syncwarp();

    // ---------------- Phase B: inverse-CDF importance sampling ----------------
    // lane handles i = lane*4 + k; z samples stay in registers.
    const float c127 = cdf[127];                  // hoisted step-128 probe (broadcast)
    float zk[4];
#pragma unroll
    for (int k = 0; k < 4; k++) {
        int i = lane * 4 + k;
        float u = (i == 127) ? 1.0f : (float)i * (1.0f / 127.0f);
        // searchsorted(cdf[0..254], u, side='right'); cb=cdf[ind-1], ca=cdf[ind]
        // (rejected probe positions strictly decrease, so last reject is cdf[ind]).
        int ind;
        float cb, ca;
        if (c127 <= u) { ind = 128; cb = c127; ca = __int_as_float(0x7f800000); }
        else           { ind = 0;   cb = 0.0f; ca = c127; }
#pragma unroll
        for (int step = 64; step >= 1; step >>= 1) {
            float cv = cdf[ind + step - 1];       // max probe idx = 255 (= +inf pad)
            if (cv <= u) { ind += step; cb = cv; }
            else         { ca = cv; }
        }
        // ind >= 1 always; ind==255 -> ca=+inf -> t=0 -> bins_b (ref denom<1e-5 path)
        float bb = zmid[ind - 1];
        float ba = zmid[min(ind, 254)];           // ind==255 reads 254 == bb
        float denom = ca - cb;
        if (denom < 1e-5f) denom = 1.0f;
        float t = __fdividef(u - cb, denom);
        zk[k] = bb + t * (ba - bb);
    }

    // ---------------- Phase C: TSDF weights ----------------
    const float* sdf_row = sdf + (size_t)ray * N_IMP;
    float4 s4 = __ldg((const float4*)(sdf_row + lane * 4));
    float s[4] = {s4.x, s4.y, s4.z, s4.w};
    float al[4];
#pragma unroll
    for (int k = 0; k < 4; k++) {
        float x = s[k] * (1.0f / TRUNC);           // exact: / 2^-6
        // sigmoid(x)*sigmoid(-x) = e*d^2, e = exp(-|x|), d = 1/(1+e)  (stable, even)
        float e = __expf(-fabsf(x));
        float d = __fdividef(1.0f, 1.0f + e);
        al[k] = e * d * d;
    }

    // first zero-crossing (argmax of sign_mask; 0 if none) via ballot + ffs
    float snext = __shfl_down_sync(FULL_MASK, s[0], 1);
    int localk = 4;                                // 4 = no crossing in this lane
    if (lane < 31 && s[3] * snext < 0.0f) localk = 3;
#pragma unroll
    for (int k = 2; k >= 0; k--) {
        if (s[k] * s[k + 1] < 0.0f) localk = k;
    }
    unsigned bal = __ballot_sync(FULL_MASK, localk < 4);
    int src = (bal != 0) ? (__ffs(bal) - 1) : 0;   // first lane with a crossing, else 0
    // candidate: owner's first-crossing z; if no crossing anywhere -> lane0's zk[0]
    int sel = (localk < 4) ? localk : 0;
    float zc = (sel & 2) ? ((sel & 1) ? zk[3] : zk[2])
                         : ((sel & 1) ? zk[1] : zk[0]);
    float zmin = __shfl_sync(FULL_MASK, zc, src);
    float thr  = zmin + TRUNC;                     // sc_factor = 1.0

    float wsum = 0.0f;
#pragma unroll
    for (int k = 0; k < 4; k++) {
        if (!(zk[k] < thr)) al[k] = 0.0f;          // trunc_mask
        wsum += al[k];
    }
#pragma unroll
    for (int off = 16; off; off >>= 1)
        wsum += __shfl_xor_sync(FULL_MASK, wsum, off);
    float inv = 1.0f / (wsum + 1e-8f);
    float w0 = al[0] * inv, w1 = al[1] * inv, w2 = al[2] * inv, w3 = al[3] * inv;

    // ---------------- Phase D: composite ----------------
    const float* rgb_row = rgbs + (size_t)ray * (N_IMP * 3) + lane * 12;
    float4 q0 = __ldg((const float4*)(rgb_row));
    float4 q1 = __ldg((const float4*)(rgb_row + 4));
    float4 q2 = __ldg((const float4*)(rgb_row + 8));

    float r   = w0 * q0.x + w1 * q0.w + w2 * q1.z + w3 * q2.y;
    float g   = w0 * q0.y + w1 * q1.x + w2 * q1.w + w3 * q2.z;
    float b   = w0 * q0.z + w1 * q1.y + w2 * q2.x + w3 * q2.w;
    float dep = w0 * zk[0] + w1 * zk[1] + w2 * zk[2] + w3 * zk[3];

    // 3 butterfly steps on all 4 accumulators -> class-(lane&3) partials
#pragma unroll
    for (int off = 16; off >= 4; off >>= 1) {
        r   += __shfl_xor_sync(FULL_MASK, r,   off);
        g   += __shfl_xor_sync(FULL_MASK, g,   off);
        b   += __shfl_xor_sync(FULL_MASK, b,   off);
        dep += __shfl_xor_sync(FULL_MASK, dep, off);
    }
    // each 4-lane group finishes one variable: lanes 0-3 r, 4-7 g, 8-11 b, 12-15 dep
    int vsel = (lane >> 2) & 3;
    float x = (vsel == 0) ? r : (vsel == 1) ? g : (vsel == 2) ? b : dep;
    x += __shfl_xor_sync(FULL_MASK, x, 1);
    x += __shfl_xor_sync(FULL_MASK, x, 2);

    float* orow = out + (size_t)ray * OUT_COLS;
    if (lane < 16 && (lane & 3) == 0) {
        int col = lane >> 2;                       // 0:r 1:g 2:b 3:depth
        float res = (col < 3) ? fminf(fmaxf(x, 0.0f), 1.0f) : x;
        orow[col] = res;                           // 4 lanes, one 16B transaction
    }
    *(float4*)(orow + 4 + lane * 4) = make_float4(w0, w1, w2, w3);
}

extern "C" void kernel_launch(void* const* d_in, const int* in_sizes, int n_in,
                              void* d_out, int out_size)
{
    const float* occ   = (const float*)d_in[0];  // [N, 256]
    const float* zvals = (const float*)d_in[1];  // [N, 256]
    const float* sdfp  = (const float*)d_in[2];  // [N, 128]
    const float* rgbs  = (const float*)d_in[3];  // [N, 128, 3]
    float* out = (float*)d_out;                  // [N, 132]

    int n_rays = in_sizes[0] / S_UNIFORM;
    int blocks = (n_rays + WARPS_PER_BLK - 1) / WARPS_PER_BLK;
    tsdf_render_kernel<<<blocks, WARPS_PER_BLK * 32>>>(occ, zvals, sdfp, rgbs, out, n_rays);
}

// round 14
// speedup vs baseline: 1.5081x; 1.0089x over previous
#include <cuda_runtime.h>
#include <math.h>

#define FULL_MASK 0xffffffffu

static constexpr int S_UNIFORM = 256;   // coarse samples per ray
static constexpr int N_IMP     = 128;   // importance samples per ray
static constexpr int OUT_COLS  = 4 + N_IMP;  // 132
static constexpr int WARPS_PER_BLK = 8;
static constexpr float TRUNC   = 0.015625f;  // 2/512*4

__global__ __launch_bounds__(WARPS_PER_BLK * 32, 8)
void tsdf_render_kernel(const float* __restrict__ occ,
                        const float* __restrict__ zvals,
                        const float* __restrict__ sdf,
                        const float* __restrict__ rgbs,
                        float* __restrict__ out,
                        int n_rays)
{
    __shared__ float cdf_s [WARPS_PER_BLK][256];  // [0..254]=cdf, [255]=+inf pad
    __shared__ float zmid_s[WARPS_PER_BLK][256];  // z midpoints [0..254]

    const int warp = threadIdx.x >> 5;
    const int lane = threadIdx.x & 31;
    const int ray  = blockIdx.x * WARPS_PER_BLK + warp;
    if (ray >= n_rays) return;

    float* cdf  = cdf_s[warp];
    float* zmid = zmid_s[warp];

    const float* occ_row = occ   + (size_t)ray * S_UNIFORM;
    const float* z_row   = zvals + (size_t)ray * S_UNIFORM;

    // ---------------- Phase A: coarse occupancy -> normalized CDF + zmid ----------------
    float4 o0 = __ldg((const float4*)(occ_row + lane * 8));
    float4 o1 = __ldg((const float4*)(occ_row + lane * 8 + 4));
    float4 zA = __ldg((const float4*)(z_row + lane * 8));
    float4 zB = __ldg((const float4*)(z_row + lane * 8 + 4));

    // z midpoints: zmid[g] = 0.5*(z[g]+z[g+1]); chunk boundary via shuffle
    float znext = __shfl_down_sync(FULL_MASK, zA.x, 1);  // lane31: self (zmid[255] unused)
    {
        float4 m0, m1;
        m0.x = 0.5f * (zA.x + zA.y);
        m0.y = 0.5f * (zA.y + zA.z);
        m0.z = 0.5f * (zA.z + zA.w);
        m0.w = 0.5f * (zA.w + zB.x);
        m1.x = 0.5f * (zB.x + zB.y);
        m1.y = 0.5f * (zB.y + zB.z);
        m1.z = 0.5f * (zB.z + zB.w);
        m1.w = 0.5f * (zB.w + znext);
        ((float4*)(zmid + lane * 8))[0] = m0;
        ((float4*)(zmid + lane * 8))[1] = m1;
    }

    float oc[8] = {o0.x, o0.y, o0.z, o0.w, o1.x, o1.y, o1.z, o1.w};
    float a[8], f[8];
#pragma unroll
    for (int j = 0; j < 8; j++) {
        float e = __expf(-10.0f * oc[j]);         // sigmoid(10*occ) = 1/(1+e)
        float d = __fdividef(1.0f, 1.0f + e);
        a[j] = d;
        f[j] = (1.0f - d) + 1e-10f;               // ref order: 1 - alpha + 1e-10
    }

    // multiplicative exclusive warp scan for transmittance
    float ptot = 1.0f;
#pragma unroll
    for (int j = 0; j < 8; j++) ptot *= f[j];
    float v = ptot;
#pragma unroll
    for (int off = 1; off < 32; off <<= 1) {
        float t = __shfl_up_sync(FULL_MASK, v, off);
        if (lane >= off) v *= t;
    }
    float pexcl = __shfl_up_sync(FULL_MASK, v, 1);
    if (lane == 0) pexcl = 1.0f;

    // masked cumsum of (w_u + 1e-5) over g in [1, 254] -> unnormalized cdf
    float trans = pexcl;
    float c[8];
    float ssum = 0.0f;
#pragma unroll
    for (int j = 0; j < 8; j++) {
        int g = lane * 8 + j;
        float w = a[j] * trans;                   // w_u[g]
        trans *= f[j];
        float wv = (g >= 1 && g <= 254) ? (w + 1e-5f) : 0.0f;
        ssum += wv;
        c[j] = ssum;
    }
    float sv = ssum;
#pragma unroll
    for (int off = 1; off < 32; off <<= 1) {
        float t = __shfl_up_sync(FULL_MASK, sv, off);
        if (lane >= off) sv += t;
    }
    float total = __shfl_sync(FULL_MASK, sv, 31);
    float sexcl = __shfl_up_sync(FULL_MASK, sv, 1);
    if (lane == 0) sexcl = 0.0f;

    float inv_total = 1.0f / total;               // total >= 254e-5 > 0
    float vals[8];
#pragma unroll
    for (int j = 0; j < 8; j++) vals[j] = (sexcl + c[j]) * inv_total;
    // g==0 -> exact 0.  g==255 -> +inf sentinel (rejects probes)
    if (lane == 31) vals[7] = __int_as_float(0x7f800000);
    ((float4*)(cdf + lane * 8))[0] = make_float4(vals[0], vals[1], vals[2], vals[3]);
    ((float4*)(cdf + lane * 8))[1] = make_float4(vals[4], vals[5], vals[6], vals[7]);
    __syncwarp();

    // ---------------- Phase B: inverse-CDF importance sampling ----------------
    // lane handles i = lane*4 + k (consecutive u's). Bin state (ind, cb, ca, bb, ba)
    // carried across k: sample stays in same bin iff u < ca (searchsorted right:
    // cdf[ind-1] <= u < cdf[ind]); u is increasing and u >= cb holds automatically.
    const float c127 = cdf[127];                  // hoisted step-128 probe (broadcast)
    const float INF  = __int_as_float(0x7f800000);
    float zk[4];
    int ind; float cb, ca, bb, ba;
    {
        float u = (float)(lane * 4) * (1.0f / 127.0f);
        if (c127 <= u) { ind = 128; cb = c127; ca = INF; }
        else           { ind = 0;   cb = 0.0f; ca = c127; }
#pragma unroll
        for (int step = 64; step >= 1; step >>= 1) {
            float cv = cdf[ind + step - 1];       // max probe idx = 255 (= +inf pad)
            if (cv <= u) { ind += step; cb = cv; }
            else         { ca = cv; }
        }
        bb = zmid[ind - 1];
        ba = zmid[min(ind, 254)];                 // ind==255 reads 254 == bb
        float denom = ca - cb;
        if (denom < 1e-5f) denom = 1.0f;
        zk[0] = bb + __fdividef(u - cb, denom) * (ba - bb);
    }
#pragma unroll
    for (int k = 1; k < 4; k++) {
        int i = lane * 4 + k;
        float u = (i == 127) ? 1.0f : (float)i * (1.0f / 127.0f);
        if (!(u < ca)) {                          // bin miss: full re-search
            if (c127 <= u) { ind = 128; cb = c127; ca = INF; }
            else           { ind = 0;   cb = 0.0f; ca = c127; }
#pragma unroll
            for (int step = 64; step >= 1; step >>= 1) {
                float cv = cdf[ind + step - 1];
                if (cv <= u) { ind += step; cb = cv; }
                else         { ca = cv; }
            }
            bb = zmid[ind - 1];
            ba = zmid[min(ind, 254)];
        }
        float denom = ca - cb;
        if (denom < 1e-5f) denom = 1.0f;
        zk[k] = bb + __fdividef(u - cb, denom) * (ba - bb);
    }

    // ---------------- Phase C: TSDF weights ----------------
    const float* sdf_row = sdf + (size_t)ray * N_IMP;
    float4 s4 = __ldg((const float4*)(sdf_row + lane * 4));
    float s[4] = {s4.x, s4.y, s4.z, s4.w};
    float al[4];
#pragma unroll
    for (int k = 0; k < 4; k++) {
        float x = s[k] * (1.0f / TRUNC);           // exact: / 2^-6
        // sigmoid(x)*sigmoid(-x) = e*d^2, e = exp(-|x|), d = 1/(1+e)  (stable, even)
        float e = __expf(-fabsf(x));
        float d = __fdividef(1.0f, 1.0f + e);
        al[k] = e * d * d;
    }

    // first zero-crossing (argmax of sign_mask; 0 if none) via ballot + ffs
    float snext = __shfl_down_sync(FULL_MASK, s[0], 1);
    int localk = 4;                                // 4 = no crossing in this lane
    if (lane < 31 && s[3] * snext < 0.0f) localk = 3;
#pragma unroll
    for (int k = 2; k >= 0; k--) {
        if (s[k] * s[k + 1] < 0.0f) localk = k;
    }
    unsigned bal = __ballot_sync(FULL_MASK, localk < 4);
    int src = (bal != 0) ? (__ffs(bal) - 1) : 0;   // first lane with a crossing, else 0
    int sel = (localk < 4) ? localk : 0;
    float zc = (sel & 2) ? ((sel & 1) ? zk[3] : zk[2])
                         : ((sel & 1) ? zk[1] : zk[0]);
    float zmin = __shfl_sync(FULL_MASK, zc, src);
    float thr  = zmin + TRUNC;                     // sc_factor = 1.0

    float wsum = 0.0f;
#pragma unroll
    for (int k = 0; k < 4; k++) {
        if (!(zk[k] < thr)) al[k] = 0.0f;          // trunc_mask
        wsum += al[k];
    }
#pragma unroll
    for (int off = 16; off; off >>= 1)
        wsum += __shfl_xor_sync(FULL_MASK, wsum, off);
    float inv = 1.0f / (wsum + 1e-8f);
    float w0 = al[0] * inv, w1 = al[1] * inv, w2 = al[2] * inv, w3 = al[3] * inv;

    // ---------------- Phase D: composite ----------------
    const float* rgb_row = rgbs + (size_t)ray * (N_IMP * 3) + lane * 12;
    float4 q0 = __ldg((const float4*)(rgb_row));
    float4 q1 = __ldg((const float4*)(rgb_row + 4));
    float4 q2 = __ldg((const float4*)(rgb_row + 8));

    float r   = w0 * q0.x + w1 * q0.w + w2 * q1.z + w3 * q2.y;
    float g   = w0 * q0.y + w1 * q1.x + w2 * q1.w + w3 * q2.z;
    float b   = w0 * q0.z + w1 * q1.y + w2 * q2.x + w3 * q2.w;
    float dep = w0 * zk[0] + w1 * zk[1] + w2 * zk[2] + w3 * zk[3];

    // butterfly 16,8 on all 4 accumulators -> 8 residual classes x 4 groups
#pragma unroll
    for (int off = 16; off >= 8; off >>= 1) {
        r   += __shfl_xor_sync(FULL_MASK, r,   off);
        g   += __shfl_xor_sync(FULL_MASK, g,   off);
        b   += __shfl_xor_sync(FULL_MASK, b,   off);
        dep += __shfl_xor_sync(FULL_MASK, dep, off);
    }
    // each 8-lane group finishes one variable: 0-7 r, 8-15 g, 16-23 b, 24-31 dep
    int vsel = lane >> 3;
    float x = (vsel == 0) ? r : (vsel == 1) ? g : (vsel == 2) ? b : dep;
    x += __shfl_xor_sync(FULL_MASK, x, 4);
    x += __shfl_xor_sync(FULL_MASK, x, 2);
    x += __shfl_xor_sync(FULL_MASK, x, 1);

    float* orow = out + (size_t)ray * OUT_COLS;
    if ((lane & 7) == 0) {
        int col = lane >> 3;                       // 0:r 1:g 2:b 3:depth
        float res = (col < 3) ? fminf(fmaxf(x, 0.0f), 1.0f) : x;
        orow[col] = res;                           // 4 lanes, one 16B transaction
    }
    *(float4*)(orow + 4 + lane * 4) = make_float4(w0, w1, w2, w3);
}

extern "C" void kernel_launch(void* const* d_in, const int* in_sizes, int n_in,
                              void* d_out, int out_size)
{
    const float* occ   = (const float*)d_in[0];  // [N, 256]
    const float* zvals = (const float*)d_in[1];  // [N, 256]
    const float* sdfp  = (const float*)d_in[2];  // [N, 128]
    const float* rgbs  = (const float*)d_in[3];  // [N, 128, 3]
    float* out = (float*)d_out;                  // [N, 132]

    int n_rays = in_sizes[0] / S_UNIFORM;
    int blocks = (n_rays + WARPS_PER_BLK - 1) / WARPS_PER_BLK;
    tsdf_render_kernel<<<blocks, WARPS_PER_BLK * 32>>>(occ, zvals, sdfp, rgbs, out, n_rays);
}

// round 17
// speedup vs baseline: 1.5505x; 1.0281x over previous
#include <cuda_runtime.h>
#include <math.h>

#define FULL_MASK 0xffffffffu

static constexpr int S_UNIFORM = 256;   // coarse samples per ray
static constexpr int N_IMP     = 128;   // importance samples per ray
static constexpr int OUT_COLS  = 4 + N_IMP;  // 132
static constexpr int WARPS_PER_BLK = 8;
static constexpr float TRUNC   = 0.015625f;  // 2/512*4

__global__ __launch_bounds__(WARPS_PER_BLK * 32, 8)
void tsdf_render_kernel(const float* __restrict__ occ,
                        const float* __restrict__ zvals,
                        const float* __restrict__ sdf,
                        const float* __restrict__ rgbs,
                        float* __restrict__ out,
                        int n_rays)
{
    __shared__ float cdf_s [WARPS_PER_BLK][256];  // [0..254]=cdf, [255]=+inf pad
    __shared__ float zmid_s[WARPS_PER_BLK][256];  // z midpoints [0..254]

    const int warp = threadIdx.x >> 5;
    const int lane = threadIdx.x & 31;
    const int ray  = blockIdx.x * WARPS_PER_BLK + warp;
    if (ray >= n_rays) return;

    float* cdf  = cdf_s[warp];
    float* zmid = zmid_s[warp];

    const float* occ_row = occ   + (size_t)ray * S_UNIFORM;
    const float* z_row   = zvals + (size_t)ray * S_UNIFORM;

    // ---------------- Phase A: coarse occupancy -> normalized CDF + zmid ----------------
    float4 o0 = __ldg((const float4*)(occ_row + lane * 8));
    float4 o1 = __ldg((const float4*)(occ_row + lane * 8 + 4));
    float4 zA = __ldg((const float4*)(z_row + lane * 8));
    float4 zB = __ldg((const float4*)(z_row + lane * 8 + 4));

    // z midpoints: zmid[g] = 0.5*(z[g]+z[g+1]); chunk boundary via shuffle
    float znext = __shfl_down_sync(FULL_MASK, zA.x, 1);  // lane31: self (zmid[255] unused)
    {
        float4 m0, m1;
        m0.x = 0.5f * (zA.x + zA.y);
        m0.y = 0.5f * (zA.y + zA.z);
        m0.z = 0.5f * (zA.z + zA.w);
        m0.w = 0.5f * (zA.w + zB.x);
        m1.x = 0.5f * (zB.x + zB.y);
        m1.y = 0.5f * (zB.y + zB.z);
        m1.z = 0.5f * (zB.z + zB.w);
        m1.w = 0.5f * (zB.w + znext);
        ((float4*)(zmid + lane * 8))[0] = m0;
        ((float4*)(zmid + lane * 8))[1] = m1;
    }

    float oc[8] = {o0.x, o0.y, o0.z, o0.w, o1.x, o1.y, o1.z, o1.w};
    float f[8];
#pragma unroll
    for (int j = 0; j < 8; j++) {
        float e = __expf(-10.0f * oc[j]);         // sigmoid(10*occ) = 1/(1+e)
        float d = __fdividef(1.0f, 1.0f + e);
        f[j] = (1.0f - d) + 1e-10f;               // ref order: 1 - alpha + 1e-10
    }

    // local inclusive prefix products P_j = f[0]*...*f[j]
    float P[8];
    P[0] = f[0];
#pragma unroll
    for (int j = 1; j < 8; j++) P[j] = P[j - 1] * f[j];

    // multiplicative exclusive warp scan -> pexcl = prod of all f before this lane
    float v = P[7];
#pragma unroll
    for (int off = 1; off < 32; off <<= 1) {
        float t = __shfl_up_sync(FULL_MASK, v, off);
        if (lane >= off) v *= t;
    }
    float pexcl = __shfl_up_sync(FULL_MASK, v, 1);
    if (lane == 0) pexcl = 1.0f;

    // Telescoped cumsum: cumsum_{1..g}(w_u + 1e-5) = f0 - T_{g+1} + g*1e-5
    //   (w_g = alpha_g*T_g = T_g - T_{g+1} + 1e-10*T_g; dropped term <= 2.5e-8 abs
    //    on a total >= 2.54e-3 -> rel perturbation <= 1e-5, inside tolerance)
    // T_{g+1} for g = 8*lane+j is pexcl * P[j].
    float f0 = __shfl_sync(FULL_MASK, f[0], 0);
    float t254 = __shfl_sync(FULL_MASK, pexcl * P[6], 31);   // T_255
    float total = (f0 - t254) + 254.0f * 1e-5f;              // >= 254e-5 > 0
    float inv_total = 1.0f / total;

    float vals[8];
#pragma unroll
    for (int j = 0; j < 8; j++) {
        int g = lane * 8 + j;
        float cu = (f0 - pexcl * P[j]) + (float)g * 1e-5f;   // unnormalized cumsum at g
        vals[j] = cu * inv_total;
    }
    if (lane == 0)  vals[0] = 0.0f;                          // g==0 exact 0
    if (lane == 31) vals[7] = __int_as_float(0x7f800000);    // g==255 +inf sentinel
    ((float4*)(cdf + lane * 8))[0] = make_float4(vals[0], vals[1], vals[2], vals[3]);
    ((float4*)(cdf + lane * 8))[1] = make_float4(vals[4], vals[5], vals[6], vals[7]);
    __syncwarp();

    // ---------------- Phase B: inverse-CDF importance sampling ----------------
    // lane handles i = lane*4 + k (consecutive u's). Bin state (ind, cb, ca, bb, ba)
    // carried across k: sample stays in same bin iff u < ca (searchsorted right:
    // cdf[ind-1] <= u < cdf[ind]); u is increasing and u >= cb holds automatically.
    const float c127 = cdf[127];                  // hoisted step-128 probe (broadcast)
    const float INF  = __int_as_float(0x7f800000);
    float zk[4];
    int ind; float cb, ca, bb, ba;
    {
        float u = (float)(lane * 4) * (1.0f / 127.0f);
        if (c127 <= u) { ind = 128; cb = c127; ca = INF; }
        else           { ind = 0;   cb = 0.0f; ca = c127; }
#pragma unroll
        for (int step = 64; step >= 1; step >>= 1) {
            float cv = cdf[ind + step - 1];       // max probe idx = 255 (= +inf pad)
            if (cv <= u) { ind += step; cb = cv; }
            else         { ca = cv; }
        }
        bb = zmid[ind - 1];
        ba = zmid[min(ind, 254)];                 // ind==255 reads 254 == bb
        float denom = ca - cb;
        if (denom < 1e-5f) denom = 1.0f;
        zk[0] = bb + __fdividef(u - cb, denom) * (ba - bb);
    }
#pragma unroll
    for (int k = 1; k < 4; k++) {
        int i = lane * 4 + k;
        float u = (i == 127) ? 1.0f : (float)i * (1.0f / 127.0f);
        if (!(u < ca)) {                          // bin miss: full re-search
            if (c127 <= u) { ind = 128; cb = c127; ca = INF; }
            else           { ind = 0;   cb = 0.0f; ca = c127; }
#pragma unroll
            for (int step = 64; step >= 1; step >>= 1) {
                float cv = cdf[ind + step - 1];
                if (cv <= u) { ind += step; cb = cv; }
                else         { ca = cv; }
            }
            bb = zmid[ind - 1];
            ba = zmid[min(ind, 254)];
        }
        float denom = ca - cb;
        if (denom < 1e-5f) denom = 1.0f;
        zk[k] = bb + __fdividef(u - cb, denom) * (ba - bb);
    }

    // ---------------- Phase C: TSDF weights ----------------
    const float* sdf_row = sdf + (size_t)ray * N_IMP;
    float4 s4 = __ldg((const float4*)(sdf_row + lane * 4));
    float s[4] = {s4.x, s4.y, s4.z, s4.w};
    float al[4];
#pragma unroll
    for (int k = 0; k < 4; k++) {
        float x = s[k] * (1.0f / TRUNC);           // exact: / 2^-6
        // sigmoid(x)*sigmoid(-x) = e*d^2, e = exp(-|x|), d = 1/(1+e)  (stable, even)
        float e = __expf(-fabsf(x));
        float d = __fdividef(1.0f, 1.0f + e);
        al[k] = e * d * d;
    }

    // first zero-crossing (argmax of sign_mask; 0 if none) via ballot + ffs
    float snext = __shfl_down_sync(FULL_MASK, s[0], 1);
    int localk = 4;                                // 4 = no crossing in this lane
    if (lane < 31 && s[3] * snext < 0.0f) localk = 3;
#pragma unroll
    for (int k = 2; k >= 0; k--) {
        if (s[k] * s[k + 1] < 0.0f) localk = k;
    }
    unsigned bal = __ballot_sync(FULL_MASK, localk < 4);
    int src = (bal != 0) ? (__ffs(bal) - 1) : 0;   // first lane with a crossing, else 0
    int sel = (localk < 4) ? localk : 0;
    float zc = (sel & 2) ? ((sel & 1) ? zk[3] : zk[2])
                         : ((sel & 1) ? zk[1] : zk[0]);
    float zmin = __shfl_sync(FULL_MASK, zc, src);
    float thr  = zmin + TRUNC;                     // sc_factor = 1.0

    float wsum = 0.0f;
#pragma unroll
    for (int k = 0; k < 4; k++) {
        if (!(zk[k] < thr)) al[k] = 0.0f;          // trunc_mask
        wsum += al[k];
    }
#pragma unroll
    for (int off = 16; off; off >>= 1)
        wsum += __shfl_xor_sync(FULL_MASK, wsum, off);
    float inv = 1.0f / (wsum + 1e-8f);
    float w0 = al[0] * inv, w1 = al[1] * inv, w2 = al[2] * inv, w3 = al[3] * inv;

    // ---------------- Phase D: composite ----------------
    const float* rgb_row = rgbs + (size_t)ray * (N_IMP * 3) + lane * 12;
    float4 q0 = __ldg((const float4*)(rgb_row));
    float4 q1 = __ldg((const float4*)(rgb_row + 4));
    float4 q2 = __ldg((const float4*)(rgb_row + 8));

    float r   = w0 * q0.x + w1 * q0.w + w2 * q1.z + w3 * q2.y;
    float g   = w0 * q0.y + w1 * q1.x + w2 * q1.w + w3 * q2.z;
    float b   = w0 * q0.z + w1 * q1.y + w2 * q2.x + w3 * q2.w;
    float dep = w0 * zk[0] + w1 * zk[1] + w2 * zk[2] + w3 * zk[3];

    // butterfly 16,8 on all 4 accumulators -> 8 residual classes x 4 groups
#pragma unroll
    for (int off = 16; off >= 8; off >>= 1) {
        r   += __shfl_xor_sync(FULL_MASK, r,   off);
        g   += __shfl_xor_sync(FULL_MASK, g,   off);
        b   += __shfl_xor_sync(FULL_MASK, b,   off);
        dep += __shfl_xor_sync(FULL_MASK, dep, off);
    }
    // each 8-lane group finishes one variable: 0-7 r, 8-15 g, 16-23 b, 24-31 dep
    int vsel = lane >> 3;
    float x = (vsel == 0) ? r : (vsel == 1) ? g : (vsel == 2) ? b : dep;
    x += __shfl_xor_sync(FULL_MASK, x, 4);
    x += __shfl_xor_sync(FULL_MASK, x, 2);
    x += __shfl_xor_sync(FULL_MASK, x, 1);

    float* orow = out + (size_t)ray * OUT_COLS;
    if ((lane & 7) == 0) {
        int col = lane >> 3;                       // 0:r 1:g 2:b 3:depth
        float res = (col < 3) ? fminf(fmaxf(x, 0.0f), 1.0f) : x;
        orow[col] = res;                           // 4 lanes, one 16B transaction
    }
    *(float4*)(orow + 4 + lane * 4) = make_float4(w0, w1, w2, w3);
}

extern "C" void kernel_launch(void* const* d_in, const int* in_sizes, int n_in,
                              void* d_out, int out_size)
{
    const float* occ   = (const float*)d_in[0];  // [N, 256]
    const float* zvals = (const float*)d_in[1];  // [N, 256]
    const float* sdfp  = (const float*)d_in[2];  // [N, 128]
    const float* rgbs  = (const float*)d_in[3];  // [N, 128, 3]
    float* out = (float*)d_out;                  // [N, 132]

    int n_rays = in_sizes[0] / S_UNIFORM;
    int blocks = (n_rays + WARPS_PER_BLK - 1) / WARPS_PER_BLK;
    tsdf_render_kernel<<<blocks, WARPS_PER_BLK * 32>>>(occ, zvals, sdfp, rgbs, out, n_rays);
}